// round 8
// baseline (speedup 1.0000x reference)
#include <cuda_runtime.h>
#include <cuda_fp16.h>
#include <math.h>
#include <stdint.h>

#define BB 128
#define SS 400
#define ENCD 1024
#define DECD 300
#define EMBD 128
#define VOCAB 50000
#define MAXOOV 50
#define PVC (VOCAB + MAXOOV)   /* 50050 */
#define RNNK (EMBD + ENCD)     /* 1152 */
#define HWK (DECD + ENCD)      /* 1324 */
#define G3 (3 * DECD)          /* 900 */
#define KPAD 1344              /* HWK padded to multiple of 32 */

// ---------------- scratch (static device globals; no allocation) ----------
__device__ __align__(256) float g_v[BB * ENCD];
__device__ __align__(256) float g_rnn[BB * RNNK];
__device__ __align__(256) float g_gx[BB * G3];
__device__ __align__(256) float g_gh[BB * G3];
__device__ __align__(256) float g_hw[BB * HWK];
__device__ __align__(256) float g_sc[BB * SS];
__device__ __align__(256) float g_a2[BB * SS];
__device__ __align__(256) float g_pgen[BB];
__device__ __align__(256) float g_logits[(size_t)BB * VOCAB];
__device__ __align__(256) __half g_Af[BB * KPAD];

// ======================= helpers ==========================================
__device__ __forceinline__ uint32_t smem_u32(const void* p) {
    uint32_t a;
    asm("{ .reg .u64 t; cvta.to.shared.u64 t, %1; cvt.u32.u64 %0, t; }"
        : "=r"(a) : "l"(p));
    return a;
}

__device__ __forceinline__ void ldmx4(uint32_t* r, uint32_t addr) {
    asm volatile("ldmatrix.sync.aligned.m8n8.x4.shared.b16 {%0,%1,%2,%3}, [%4];"
                 : "=r"(r[0]), "=r"(r[1]), "=r"(r[2]), "=r"(r[3]) : "r"(addr));
}

__device__ __forceinline__ void mma16816h(float* d, const uint32_t* a,
                                          uint32_t b0, uint32_t b1) {
    asm volatile(
        "mma.sync.aligned.m16n8k16.row.col.f32.f16.f16.f32 "
        "{%0,%1,%2,%3}, {%4,%5,%6,%7}, {%8,%9}, {%0,%1,%2,%3};"
        : "+f"(d[0]), "+f"(d[1]), "+f"(d[2]), "+f"(d[3])
        : "r"(a[0]), "r"(a[1]), "r"(a[2]), "r"(a[3]), "r"(b0), "r"(b1));
}

__device__ __forceinline__ void cp16(uint32_t dst, const void* src) {
    asm volatile("cp.async.cg.shared.global [%0], [%1], 16;"
                 :: "r"(dst), "l"(src) : "memory");
}
__device__ __forceinline__ void cp_commit() {
    asm volatile("cp.async.commit_group;" ::: "memory");
}
__device__ __forceinline__ void cp_wait0() {
    asm volatile("cp.async.wait_group 0;" ::: "memory");
}

// fp32x4 -> fp16x4 packed store (8 bytes)
__device__ __forceinline__ void cvt_store_h4(__half* dst, float4 v) {
    __half2 a = __floats2half2_rn(v.x, v.y);
    __half2 b = __floats2half2_rn(v.z, v.w);
    uint32_t ua, ub;
    ua = *(uint32_t*)&a;
    ub = *(uint32_t*)&b;
    *(uint2*)dst = make_uint2(ua, ub);
}

// convert A (g_hw fp32) -> g_Af fp16, zero-padded to KPAD
__global__ void convA_kernel()
{
    int b = blockIdx.x;
    for (int k = threadIdx.x; k < KPAD; k += blockDim.x) {
        float x = (k < HWK) ? g_hw[(size_t)b * HWK + k] : 0.f;
        g_Af[(size_t)b * KPAD + k] = __float2half_rn(x);
    }
}

// ====================================================================
// Tensor-core logits GEMM: C[128,N] = A[128,K]*B[N,K]^T + bias, fp16 MMA.
// Tile: M=128 x N=64 (782 CTAs: finer wave quantization), 8 warps with
// 32x32 microtiles. B prefetch distance = 2 (LDG for chunk c+2 issued at
// iteration c, consumed at c+1) -> a full iteration of DRAM latency cover.
// Loop unrolled x2 so both register staging slots are statically indexed.
// ====================================================================
#define CH 32
#define NCH (KPAD / CH)             /* 42 (even) */
#define ASTRIDE 40                  /* halves per smem row (LDSM conflict-free) */
#define A_BYTES (128 * ASTRIDE * 2) /* 10240 */
#define B_BYTES (64 * ASTRIDE * 2)  /* 5120 */
#define BUF_B (A_BYTES + B_BYTES)   /* 15360 per stage */
#define MM_SMEM (2 * BUF_B)         /* 30720 */

__global__ __launch_bounds__(256)
void gemm_mma(const float* __restrict__ B, int ldb,
              float* __restrict__ C, int ldc,
              const float* __restrict__ bias, int N, int K)
{
    extern __shared__ char smem[];
    const uint32_t sbase = smem_u32(smem);
    const int tid = threadIdx.x;
    const int wid = tid >> 5, lid = tid & 31;
    const int warp_m = (wid >> 1) * 32;   // 0,32,64,96
    const int warp_n = (wid & 1) * 32;    // 0,32
    const int bn = blockIdx.x * 64;

    float acc[2][4][4] = {};
    float4 stB0[2], stB1[2];

    // cp.async A tile: 128 rows x 32 halves (64 B/row); 32 B per thread
    const int a_half = tid >> 7;          // which 32B half of the row
    const int a_row = tid & 127;
    auto cpA = [&](int c, int buf) {
        uint32_t dst = sbase + buf * BUF_B + a_row * (ASTRIDE * 2) + a_half * 32;
        const char* src = (const char*)(g_Af + (size_t)a_row * KPAD + c * CH) + a_half * 32;
        cp16(dst, src);
        cp16(dst + 16, src + 16);
    };

    // B tile 64 rows x 32 floats = 512 float4; 2 per thread
    auto ldgB = [&](int c, float4* st) {
        const int kb = c * CH;
#pragma unroll
        for (int t = 0; t < 2; t++) {
            int idx = tid + t * 256;
            int row = idx >> 3;
            int c4 = (idx & 7) << 2;
            int gk = kb + c4;
            float4 v = make_float4(0.f, 0.f, 0.f, 0.f);
            if (gk < K) {                 // K % 4 == 0
                int n = bn + row;
                if (n < N) v = *(const float4*)(B + (size_t)n * ldb + gk);
            }
            st[t] = v;
        }
    };
    auto stsB = [&](const float4* st, int buf) {
        __half* Bf = (__half*)(smem + buf * BUF_B + A_BYTES);
#pragma unroll
        for (int t = 0; t < 2; t++) {
            int idx = tid + t * 256;
            int row = idx >> 3;
            int c4 = (idx & 7) << 2;
            cvt_store_h4(Bf + row * ASTRIDE + c4, st[t]);
        }
    };

    auto compute_chunk = [&](int buf) {
        const uint32_t Af = sbase + buf * BUF_B;
        const uint32_t Bf = Af + A_BYTES;
        const int lrow = lid & 15;
        const int lcol = (lid >> 4) << 3;
#pragma unroll
        for (int kk = 0; kk < CH; kk += 16) {
            uint32_t b0[4], b1[4];
            {
                uint32_t o0 = (uint32_t)(((warp_n + 0  + lrow) * ASTRIDE + kk + lcol) * 2);
                uint32_t o1 = (uint32_t)(((warp_n + 16 + lrow) * ASTRIDE + kk + lcol) * 2);
                ldmx4(b0, Bf + o0);
                ldmx4(b1, Bf + o1);
            }
#pragma unroll
            for (int fm = 0; fm < 2; fm++) {
                uint32_t ah[4];
                uint32_t ao = (uint32_t)(((warp_m + fm * 16 + lrow) * ASTRIDE + kk + lcol) * 2);
                ldmx4(ah, Af + ao);
                mma16816h(acc[fm][0], ah, b0[0], b0[2]);
                mma16816h(acc[fm][1], ah, b0[1], b0[3]);
                mma16816h(acc[fm][2], ah, b1[0], b1[2]);
                mma16816h(acc[fm][3], ah, b1[1], b1[3]);
            }
        }
    };

    // prologue: B0, B1 in flight; A0 + B0 staged to buf0
    ldgB(0, stB0);
    ldgB(1, stB1);
    cpA(0, 0); cp_commit();
    stsB(stB0, 0);
    cp_wait0();
    __syncthreads();

    // main loop, 2 chunks per iteration (static slot indexing)
    for (int c = 0; c < NCH; c += 2) {
        // even half: compute chunk c from buf0
        if (c + 2 < NCH) ldgB(c + 2, stB0);
        {   // c+1 < NCH always (NCH even)
            cpA(c + 1, 1); cp_commit();
            stsB(stB1, 1);
        }
        compute_chunk(0);
        cp_wait0();
        __syncthreads();
        // odd half: compute chunk c+1 from buf1
        if (c + 3 < NCH) ldgB(c + 3, stB1);
        if (c + 2 < NCH) {
            cpA(c + 2, 0); cp_commit();
            stsB(stB0, 0);
        }
        compute_chunk(1);
        if (c + 2 < NCH) {
            cp_wait0();
            __syncthreads();
        }
    }

    // epilogue
    const int erow = lid >> 2;
    const int ecol = (lid & 3) << 1;
#pragma unroll
    for (int fm = 0; fm < 2; fm++) {
#pragma unroll
        for (int fn = 0; fn < 4; fn++) {
            int row = warp_m + fm * 16 + erow;
            int col = bn + warp_n + fn * 8 + ecol;
            if (col < N) {    // col even, N even -> col+1 < N too
                float b0 = bias[col], b1 = bias[col + 1];
                float* d = acc[fm][fn];
                *(float2*)(C + (size_t)row * ldc + col) =
                    make_float2(d[0] + b0, d[1] + b1);
                *(float2*)(C + (size_t)(row + 8) * ldc + col) =
                    make_float2(d[2] + b0, d[3] + b1);
            }
        }
    }
}

// ====================================================================
// Small-GEMM: C[M,N] = A[M,K]*B[N,K]^T (+bias). Warp computes 8 m-rows
// x 4 n-cols (B loads reused 8x). grid = (ceil(N/32), M/8), 256 thr.
// ====================================================================
__global__ __launch_bounds__(256)
void gemm_warp8m(const float* __restrict__ A, int lda,
                 const float* __restrict__ B, int ldb,
                 float* __restrict__ C, int ldc,
                 const float* __restrict__ bias, int N, int K)
{
    const int m0 = blockIdx.y * 8;
    const int warp = threadIdx.x >> 5, lane = threadIdx.x & 31;
    const int n0 = blockIdx.x * 32 + warp * 4;
    if (n0 >= N) return;
    const float4* b0 = (const float4*)(B + (size_t)(n0 + 0) * ldb);
    const float4* b1 = (const float4*)(B + (size_t)(n0 + 1) * ldb);
    const float4* b2 = (const float4*)(B + (size_t)(n0 + 2) * ldb);
    const float4* b3 = (const float4*)(B + (size_t)(n0 + 3) * ldb);
    const int K4 = K >> 2;
    float acc[8][4] = {};
    for (int i = lane; i < K4; i += 32) {
        float4 v0 = b0[i], v1 = b1[i], v2 = b2[i], v3 = b3[i];
#pragma unroll
        for (int mi = 0; mi < 8; mi++) {
            float4 av = *(const float4*)(A + (size_t)(m0 + mi) * lda + i * 4);
            acc[mi][0] = fmaf(av.x, v0.x, fmaf(av.y, v0.y, fmaf(av.z, v0.z, fmaf(av.w, v0.w, acc[mi][0]))));
            acc[mi][1] = fmaf(av.x, v1.x, fmaf(av.y, v1.y, fmaf(av.z, v1.z, fmaf(av.w, v1.w, acc[mi][1]))));
            acc[mi][2] = fmaf(av.x, v2.x, fmaf(av.y, v2.y, fmaf(av.z, v2.z, fmaf(av.w, v2.w, acc[mi][2]))));
            acc[mi][3] = fmaf(av.x, v3.x, fmaf(av.y, v3.y, fmaf(av.z, v3.z, fmaf(av.w, v3.w, acc[mi][3]))));
        }
    }
#pragma unroll
    for (int mi = 0; mi < 8; mi++)
#pragma unroll
        for (int j = 0; j < 4; j++) {
            float a = acc[mi][j];
#pragma unroll
            for (int o = 16; o; o >>= 1) a += __shfl_xor_sync(0xffffffffu, a, o);
            acc[mi][j] = a;
        }
    if (lane == 0) {
#pragma unroll
        for (int mi = 0; mi < 8; mi++) {
            float* c = C + (size_t)(m0 + mi) * ldc + n0;
            if (bias) {
                c[0] = acc[mi][0] + bias[n0 + 0];
                c[1] = acc[mi][1] + bias[n0 + 1];
                c[2] = acc[mi][2] + bias[n0 + 2];
                c[3] = acc[mi][3] + bias[n0 + 3];
            } else {
                c[0] = acc[mi][0]; c[1] = acc[mi][1];
                c[2] = acc[mi][2]; c[3] = acc[mi][3];
            }
        }
    }
}

// ---------------- attention (3 phases for full BW) -------------------------
// Phase 1: scores[b,s] = dot(enc[b,s,:], v[b,:]) (+pad mask). grid (50, BB).
__global__ __launch_bounds__(256)
void attn_scores(const float* __restrict__ enc, const float* __restrict__ v,
                 const unsigned char* __restrict__ pad, float* __restrict__ sc)
{
    const int b = blockIdx.y;
    const int lane = threadIdx.x & 31, warp = threadIdx.x >> 5;
    const int s = blockIdx.x * 8 + warp;
    __shared__ __align__(16) float vsh[ENCD];
    ((float4*)vsh)[threadIdx.x] = ((const float4*)(v + (size_t)b * ENCD))[threadIdx.x];
    __syncthreads();
    const float4* row = (const float4*)(enc + ((size_t)b * SS + s) * ENCD);
    const float4* vv = (const float4*)vsh;
    float acc = 0.f;
#pragma unroll
    for (int i = 0; i < ENCD / 128; i++) {
        float4 e4 = row[lane + 32 * i];
        float4 v4 = vv[lane + 32 * i];
        acc = fmaf(e4.x, v4.x, acc);
        acc = fmaf(e4.y, v4.y, acc);
        acc = fmaf(e4.z, v4.z, acc);
        acc = fmaf(e4.w, v4.w, acc);
    }
#pragma unroll
    for (int o = 16; o; o >>= 1) acc += __shfl_xor_sync(0xffffffffu, acc, o);
    if (lane == 0)
        sc[(size_t)b * SS + s] = pad[(size_t)b * SS + s] ? -INFINITY : acc;
}

// Phase 2: softmax over S in place (+optional copy). grid BB, 128 thr.
__global__ __launch_bounds__(128)
void attn_softmax(float* __restrict__ sc, float* __restrict__ a_out)
{
    const int b = blockIdx.x, tid = threadIdx.x;
    const int lane = tid & 31, warp = tid >> 5;
    __shared__ float buf[SS];
    __shared__ float red[4];
    float* scb = sc + (size_t)b * SS;
    for (int i = tid; i < SS; i += 128) buf[i] = scb[i];
    __syncthreads();
    float m = -INFINITY;
    for (int i = tid; i < SS; i += 128) m = fmaxf(m, buf[i]);
#pragma unroll
    for (int o = 16; o; o >>= 1) m = fmaxf(m, __shfl_xor_sync(0xffffffffu, m, o));
    if (lane == 0) red[warp] = m;
    __syncthreads();
    m = fmaxf(fmaxf(red[0], red[1]), fmaxf(red[2], red[3]));
    float s = 0.f;
    for (int i = tid; i < SS; i += 128) {
        float e = __expf(buf[i] - m);
        buf[i] = e;
        s += e;
    }
#pragma unroll
    for (int o = 16; o; o >>= 1) s += __shfl_xor_sync(0xffffffffu, s, o);
    __syncthreads();
    if (lane == 0) red[warp] = s;
    __syncthreads();
    float inv = 1.f / (red[0] + red[1] + red[2] + red[3]);
    for (int i = tid; i < SS; i += 128) {
        float a = buf[i] * inv;
        scb[i] = a;
        if (a_out) a_out[(size_t)b * SS + i] = a;
    }
}

// Phase 3: weighted[b,e] = sum_s a[s] * enc[b,s,e]. grid (8, BB), 128 thr.
__global__ __launch_bounds__(128)
void attn_weighted(const float* __restrict__ enc, const float* __restrict__ sc,
                   float* __restrict__ wout, int wstride)
{
    const int b = blockIdx.y;
    const int e = blockIdx.x * 128 + threadIdx.x;
    __shared__ float a[SS];
    for (int i = threadIdx.x; i < SS; i += 128) a[i] = sc[(size_t)b * SS + i];
    __syncthreads();
    const float* p = enc + (size_t)b * SS * ENCD + e;
    float w0 = 0.f, w1 = 0.f, w2 = 0.f, w3 = 0.f;
    float w4 = 0.f, w5 = 0.f, w6 = 0.f, w7 = 0.f;
#pragma unroll 1
    for (int s = 0; s < SS; s += 8) {
        w0 = fmaf(a[s + 0], p[(size_t)(s + 0) * ENCD], w0);
        w1 = fmaf(a[s + 1], p[(size_t)(s + 1) * ENCD], w1);
        w2 = fmaf(a[s + 2], p[(size_t)(s + 2) * ENCD], w2);
        w3 = fmaf(a[s + 3], p[(size_t)(s + 3) * ENCD], w3);
        w4 = fmaf(a[s + 4], p[(size_t)(s + 4) * ENCD], w4);
        w5 = fmaf(a[s + 5], p[(size_t)(s + 5) * ENCD], w5);
        w6 = fmaf(a[s + 6], p[(size_t)(s + 6) * ENCD], w6);
        w7 = fmaf(a[s + 7], p[(size_t)(s + 7) * ENCD], w7);
    }
    wout[(size_t)b * wstride + e] = ((w0 + w1) + (w2 + w3)) + ((w4 + w5) + (w6 + w7));
}

// ---------------- small elementwise / glue kernels -------------------------
__global__ void embed_copy(const float* __restrict__ emb)
{
    int i = blockIdx.x * blockDim.x + threadIdx.x;
    if (i < BB * EMBD) {
        int b = i / EMBD, j = i - b * EMBD;
        g_rnn[(size_t)b * RNNK + j] = emb[i];
    }
}

__global__ void gru_combine(const float* __restrict__ h1,
                            float* __restrict__ out_h, int write_out)
{
    int i = blockIdx.x * blockDim.x + threadIdx.x;
    if (i >= BB * DECD) return;
    int b = i / DECD, j = i - b * DECD;
    const float* gx = g_gx + (size_t)b * G3;
    const float* gh = g_gh + (size_t)b * G3;
    float r = 1.f / (1.f + __expf(-(gx[j] + gh[j])));
    float z = 1.f / (1.f + __expf(-(gx[j + DECD] + gh[j + DECD])));
    float n = tanhf(gx[j + 2 * DECD] + r * gh[j + 2 * DECD]);
    float h = (1.f - z) * n + z * h1[i];
    g_hw[(size_t)b * HWK + j] = h;
    if (write_out) out_h[i] = h;
}

__global__ __launch_bounds__(128)
void pgen_kernel(const float* __restrict__ Wp, const float* __restrict__ bp)
{
    int b = blockIdx.x, tid = threadIdx.x;
    int lane = tid & 31, warp = tid >> 5;
    __shared__ float red[4];
    const float* hwb = g_hw + (size_t)b * HWK;
    float acc = 0.f;
    for (int i = tid; i < HWK; i += 128) acc = fmaf(hwb[i], Wp[i], acc);
#pragma unroll
    for (int o = 16; o; o >>= 1) acc += __shfl_xor_sync(0xffffffffu, acc, o);
    if (lane == 0) red[warp] = acc;
    __syncthreads();
    if (tid == 0) {
        float t = red[0] + red[1] + red[2] + red[3] + bp[0];
        g_pgen[b] = 1.f / (1.f + __expf(-t));
    }
}

// online max+sum softmax over VOCAB, then scaled write. grid BB, 1024 thr.
__global__ __launch_bounds__(1024)
void pvocab_kernel(float* __restrict__ pout)
{
    int b = blockIdx.x, tid = threadIdx.x;
    int lane = tid & 31, warp = tid >> 5;
    __shared__ float red_m[32], red_s[32];
    __shared__ float bc[2];
    const float* lg = g_logits + (size_t)b * VOCAB;

    float m = -INFINITY, s = 0.f;
    for (int i = tid; i < VOCAB; i += 1024) {
        float x = lg[i];
        float mo = m;
        m = fmaxf(m, x);
        s = s * __expf(mo - m) + __expf(x - m);
    }
#pragma unroll
    for (int o = 16; o; o >>= 1) {
        float m2 = __shfl_xor_sync(0xffffffffu, m, o);
        float s2 = __shfl_xor_sync(0xffffffffu, s, o);
        float M = fmaxf(m, m2);
        s = s * __expf(m - M) + s2 * __expf(m2 - M);
        m = M;
    }
    if (lane == 0) { red_m[warp] = m; red_s[warp] = s; }
    __syncthreads();
    if (tid == 0) {
        float M = red_m[0], S = red_s[0];
        for (int w = 1; w < 32; w++) {
            float M2 = fmaxf(M, red_m[w]);
            S = S * __expf(M - M2) + red_s[w] * __expf(red_m[w] - M2);
            M = M2;
        }
        bc[0] = M; bc[1] = S;
    }
    __syncthreads();
    m = bc[0];
    float scale = g_pgen[b] / bc[1];
    float* row = pout + (size_t)b * PVC;
    for (int i = tid; i < VOCAB; i += 1024) row[i] = __expf(lg[i] - m) * scale;
    for (int i = VOCAB + tid; i < PVC; i += 1024) row[i] = 0.f;
}

__global__ void scatter_kernel(const int* __restrict__ src, float* __restrict__ pout)
{
    int i = blockIdx.x * blockDim.x + threadIdx.x;
    if (i >= BB * SS) return;
    int b = i / SS;
    float val = (1.f - g_pgen[b]) * g_a2[i];
    atomicAdd(pout + (size_t)b * PVC + src[i], val);
}

// ---------------- launch ---------------------------------------------------
extern "C" void kernel_launch(void* const* d_in, const int* in_sizes, int n_in,
                              void* d_out, int out_size)
{
    int off = (n_in >= 16) ? 0 : -1;
    const float* embedded = (const float*)d_in[0];
    const float* enc      = (const float*)d_in[1];
    const float* h1       = (const float*)d_in[2];
    const unsigned char* pad = (const unsigned char*)d_in[3];
    const int*   src      = (const int*)d_in[5 + off];
    const float* W_attn1  = (const float*)d_in[6 + off];
    const float* W_attn2  = (const float*)d_in[7 + off];
    const float* W_ih     = (const float*)d_in[8 + off];
    const float* W_hh     = (const float*)d_in[9 + off];
    const float* b_ih     = (const float*)d_in[10 + off];
    const float* b_hh     = (const float*)d_in[11 + off];
    const float* W_out    = (const float*)d_in[12 + off];
    const float* b_out    = (const float*)d_in[13 + off];
    const float* W_p      = (const float*)d_in[14 + off];
    const float* b_p      = (const float*)d_in[15 + off];
    float* pout = (float*)d_out;

    float *v, *rnn, *gx, *gh, *hw, *logits, *sc, *a2;
    cudaGetSymbolAddress((void**)&v, g_v);
    cudaGetSymbolAddress((void**)&rnn, g_rnn);
    cudaGetSymbolAddress((void**)&gx, g_gx);
    cudaGetSymbolAddress((void**)&gh, g_gh);
    cudaGetSymbolAddress((void**)&hw, g_hw);
    cudaGetSymbolAddress((void**)&logits, g_logits);
    cudaGetSymbolAddress((void**)&sc, g_sc);
    cudaGetSymbolAddress((void**)&a2, g_a2);

    cudaFuncSetAttribute(gemm_mma, cudaFuncAttributeMaxDynamicSharedMemorySize, MM_SMEM);

    // 1. rnn[:, 0:EMB] = embedded
    embed_copy<<<(BB * EMBD + 255) / 256, 256>>>(embedded);
    // 2. gh = h1 @ W_hh^T + b_hh
    gemm_warp8m<<<dim3((G3 + 31) / 32, BB / 8), 256>>>(h1, DECD, W_hh, DECD,
                                                       gh, G3, b_hh, G3, DECD);
    // 3. v1 = h1 @ W_attn1^T
    gemm_warp8m<<<dim3(ENCD / 32, BB / 8), 256>>>(h1, DECD, W_attn1, DECD,
                                                  v, ENCD, nullptr, ENCD, DECD);
    // 4. attention 1 -> weighted1 into rnn[:, EMB:]
    attn_scores<<<dim3(SS / 8, BB), 256>>>(enc, v, pad, sc);
    attn_softmax<<<BB, 128>>>(sc, nullptr);
    attn_weighted<<<dim3(ENCD / 128, BB), 128>>>(enc, sc, rnn + EMBD, RNNK);
    // 5. gx = rnn @ W_ih^T + b_ih
    gemm_warp8m<<<dim3((G3 + 31) / 32, BB / 8), 256>>>(rnn, RNNK, W_ih, RNNK,
                                                       gx, G3, b_ih, G3, RNNK);
    // 6. GRU combine -> hw[:, 0:DEC] (= h_new)
    int wtail = (out_size >= BB * PVC + BB * DECD) ? 1 : 0;
    gru_combine<<<(BB * DECD + 255) / 256, 256>>>(h1, pout + (size_t)BB * PVC, wtail);
    // 7. v2 = h_new @ W_attn2^T
    gemm_warp8m<<<dim3(ENCD / 32, BB / 8), 256>>>(hw, HWK, W_attn2, DECD,
                                                  v, ENCD, nullptr, ENCD, DECD);
    // 8. attention 2 -> weighted2 into hw[:, DEC:], save a2
    attn_scores<<<dim3(SS / 8, BB), 256>>>(enc, v, pad, sc);
    attn_softmax<<<BB, 128>>>(sc, a2);
    attn_weighted<<<dim3(ENCD / 128, BB), 128>>>(enc, sc, hw + DECD, HWK);
    // 9. p_gen
    pgen_kernel<<<BB, 128>>>(W_p, b_p);
    // 10. convert A once (fp16), then logits = hw @ W_out^T + b_out
    convA_kernel<<<BB, 256>>>();
    gemm_mma<<<dim3((VOCAB + 63) / 64), 256, MM_SMEM>>>(W_out, HWK, logits,
                                                        VOCAB, b_out, VOCAB, HWK);
    // 11. p_out[:, :VOCAB] = p_gen * softmax(logits); ext cols zeroed
    pvocab_kernel<<<BB, 1024>>>(pout);
    // 12. scatter-add (1-p_gen)*a2 at source ids
    scatter_kernel<<<(BB * SS + 255) / 256, 256>>>(src, pout);
}

// round 10
// speedup vs baseline: 1.1288x; 1.1288x over previous
#include <cuda_runtime.h>
#include <cuda_fp16.h>
#include <math.h>
#include <stdint.h>

#define BB 128
#define SS 400
#define ENCD 1024
#define DECD 300
#define EMBD 128
#define VOCAB 50000
#define MAXOOV 50
#define PVC (VOCAB + MAXOOV)   /* 50050 */
#define RNNK (EMBD + ENCD)     /* 1152 */
#define HWK (DECD + ENCD)      /* 1324 */
#define G3 (3 * DECD)          /* 900 */
#define KPAD 1344              /* HWK padded to multiple of 32 */
#define NSPLIT 16              /* attention s-splits per batch row */
#define SROWS (SS / NSPLIT)    /* 25 rows per split */
#define PVCH 50                /* pvocab chunks (1000 logits each) */

// ---------------- scratch (static device globals; no allocation) ----------
__device__ __align__(256) float g_v[BB * ENCD];
__device__ __align__(256) float g_rnn[BB * RNNK];
__device__ __align__(256) float g_gx[BB * G3];
__device__ __align__(256) float g_gh[BB * G3];
__device__ __align__(256) float g_hw[BB * HWK];
__device__ __align__(256) float g_sc[BB * SS];
__device__ __align__(256) float g_a2[BB * SS];
__device__ __align__(256) float g_pgen[BB];
__device__ __align__(256) float g_logits[(size_t)BB * VOCAB];
__device__ __align__(256) __half g_Af[BB * KPAD];
__device__ __align__(256) float g_wpart[BB * NSPLIT * ENCD];   /* 8.4 MB */
__device__ __align__(256) float2 g_ams[BB * NSPLIT];
__device__ __align__(256) float g_pm[BB * PVCH];
__device__ __align__(256) float g_ps[BB * PVCH];
__device__ __align__(256) float2 g_pms[BB];

// ======================= helpers ==========================================
__device__ __forceinline__ uint32_t smem_u32(const void* p) {
    uint32_t a;
    asm("{ .reg .u64 t; cvta.to.shared.u64 t, %1; cvt.u32.u64 %0, t; }"
        : "=r"(a) : "l"(p));
    return a;
}

__device__ __forceinline__ void ldmx4(uint32_t* r, uint32_t addr) {
    asm volatile("ldmatrix.sync.aligned.m8n8.x4.shared.b16 {%0,%1,%2,%3}, [%4];"
                 : "=r"(r[0]), "=r"(r[1]), "=r"(r[2]), "=r"(r[3]) : "r"(addr));
}

__device__ __forceinline__ void mma16816h(float* d, const uint32_t* a,
                                          uint32_t b0, uint32_t b1) {
    asm volatile(
        "mma.sync.aligned.m16n8k16.row.col.f32.f16.f16.f32 "
        "{%0,%1,%2,%3}, {%4,%5,%6,%7}, {%8,%9}, {%0,%1,%2,%3};"
        : "+f"(d[0]), "+f"(d[1]), "+f"(d[2]), "+f"(d[3])
        : "r"(a[0]), "r"(a[1]), "r"(a[2]), "r"(a[3]), "r"(b0), "r"(b1));
}

__device__ __forceinline__ void cp16(uint32_t dst, const void* src) {
    asm volatile("cp.async.cg.shared.global [%0], [%1], 16;"
                 :: "r"(dst), "l"(src) : "memory");
}
__device__ __forceinline__ void cp_commit() {
    asm volatile("cp.async.commit_group;" ::: "memory");
}
__device__ __forceinline__ void cp_wait0() {
    asm volatile("cp.async.wait_group 0;" ::: "memory");
}

// fp32x4 -> fp16x4 packed store (8 bytes)
__device__ __forceinline__ void cvt_store_h4(__half* dst, float4 v) {
    __half2 a = __floats2half2_rn(v.x, v.y);
    __half2 b = __floats2half2_rn(v.z, v.w);
    uint32_t ua, ub;
    ua = *(uint32_t*)&a;
    ub = *(uint32_t*)&b;
    *(uint2*)dst = make_uint2(ua, ub);
}

// convert A (g_hw fp32) -> g_Af fp16, zero-padded to KPAD
__global__ void convA_kernel()
{
    int b = blockIdx.x;
    for (int k = threadIdx.x; k < KPAD; k += blockDim.x) {
        float x = (k < HWK) ? g_hw[(size_t)b * HWK + k] : 0.f;
        g_Af[(size_t)b * KPAD + k] = __float2half_rn(x);
    }
}

// ====================================================================
// Tensor-core logits GEMM (round-7 config — at the legacy HMMA pipe
// floor): C[128,N] = A[128,K]*B[N,K]^T + bias, fp16 single MMA.
// ====================================================================
#define CH 32
#define NCH (KPAD / CH)             /* 42 */
#define ASTRIDE 40                  /* halves per smem row */
#define ARR_B (128 * ASTRIDE * 2)   /* 10240 bytes per array */
#define BUF_B (2 * ARR_B)           /* Af, Bf = 20480 */
#define MM_SMEM (2 * BUF_B)         /* 40960 */

__global__ __launch_bounds__(256, 2)
void gemm_mma(const float* __restrict__ B, int ldb,
              float* __restrict__ C, int ldc,
              const float* __restrict__ bias, int N, int K)
{
    extern __shared__ char smem[];
    const uint32_t sbase = smem_u32(smem);
    const int tid = threadIdx.x;
    const int wid = tid >> 5, lid = tid & 31;
    const int warp_m = (wid >> 2) * 64;   // 0, 64
    const int warp_n = (wid & 3) * 32;    // 0..96
    const int bn = blockIdx.x * 128;

    float acc[4][4][4] = {};
    float4 stB[4];

    const int a_half = tid >> 7;
    const int a_row = tid & 127;
    auto cpA = [&](int c, int buf) {
        uint32_t dst = sbase + buf * BUF_B + a_row * (ASTRIDE * 2) + a_half * 32;
        const char* src = (const char*)(g_Af + (size_t)a_row * KPAD + c * CH) + a_half * 32;
        cp16(dst, src);
        cp16(dst + 16, src + 16);
    };

    auto ldgB = [&](int c) {
        const int kb = c * CH;
#pragma unroll
        for (int t = 0; t < 4; t++) {
            int idx = tid + t * 256;
            int row = idx >> 3;
            int c4 = (idx & 7) << 2;
            int gk = kb + c4;
            float4 v = make_float4(0.f, 0.f, 0.f, 0.f);
            if (gk < K) {                 // K % 4 == 0
                int n = bn + row;
                if (n < N) v = *(const float4*)(B + (size_t)n * ldb + gk);
            }
            stB[t] = v;
        }
    };
    auto stsB = [&](int buf) {
        __half* Bf = (__half*)(smem + buf * BUF_B + ARR_B);
#pragma unroll
        for (int t = 0; t < 4; t++) {
            int idx = tid + t * 256;
            int row = idx >> 3;
            int c4 = (idx & 7) << 2;
            cvt_store_h4(Bf + row * ASTRIDE + c4, stB[t]);
        }
    };

    auto compute_chunk = [&](int buf) {
        const uint32_t Af = sbase + buf * BUF_B;
        const uint32_t Bf = Af + ARR_B;
        const int lrow = lid & 15;
        const int lcol = (lid >> 4) << 3;
#pragma unroll
        for (int kk = 0; kk < CH; kk += 16) {
            uint32_t b0[4], b1[4];
            {
                uint32_t o0 = (uint32_t)(((warp_n + 0  + lrow) * ASTRIDE + kk + lcol) * 2);
                uint32_t o1 = (uint32_t)(((warp_n + 16 + lrow) * ASTRIDE + kk + lcol) * 2);
                ldmx4(b0, Bf + o0);
                ldmx4(b1, Bf + o1);
            }
#pragma unroll
            for (int fm = 0; fm < 4; fm++) {
                uint32_t ah[4];
                uint32_t ao = (uint32_t)(((warp_m + fm * 16 + lrow) * ASTRIDE + kk + lcol) * 2);
                ldmx4(ah, Af + ao);
                mma16816h(acc[fm][0], ah, b0[0], b0[2]);
                mma16816h(acc[fm][1], ah, b0[1], b0[3]);
                mma16816h(acc[fm][2], ah, b1[0], b1[2]);
                mma16816h(acc[fm][3], ah, b1[1], b1[3]);
            }
        }
    };

    cpA(0, 0); cp_commit();
    ldgB(0);
    stsB(0);
    cp_wait0();
    __syncthreads();

    for (int c = 0; c < NCH; c++) {
        const int buf = c & 1, nb = buf ^ 1;
        if (c + 1 < NCH) {
            cpA(c + 1, nb); cp_commit();
            ldgB(c + 1);
        }
        compute_chunk(buf);
        if (c + 1 < NCH) {
            stsB(nb);
            cp_wait0();
        }
        __syncthreads();
    }

    const int erow = lid >> 2;
    const int ecol = (lid & 3) << 1;
#pragma unroll
    for (int fm = 0; fm < 4; fm++) {
#pragma unroll
        for (int fn = 0; fn < 4; fn++) {
            int row = warp_m + fm * 16 + erow;
            int col = bn + warp_n + fn * 8 + ecol;
            if (col < N) {
                float b0 = bias[col], b1 = bias[col + 1];
                float* d = acc[fm][fn];
                *(float2*)(C + (size_t)row * ldc + col) =
                    make_float2(d[0] + b0, d[1] + b1);
                *(float2*)(C + (size_t)(row + 8) * ldc + col) =
                    make_float2(d[2] + b0, d[3] + b1);
            }
        }
    }
}

// ====================================================================
// Small-GEMM: warp computes 8 m-rows x 4 n-cols. grid (ceil(N/32), M/8).
// ====================================================================
__global__ __launch_bounds__(256)
void gemm_warp8m(const float* __restrict__ A, int lda,
                 const float* __restrict__ B, int ldb,
                 float* __restrict__ C, int ldc,
                 const float* __restrict__ bias, int N, int K)
{
    const int m0 = blockIdx.y * 8;
    const int warp = threadIdx.x >> 5, lane = threadIdx.x & 31;
    const int n0 = blockIdx.x * 32 + warp * 4;
    if (n0 >= N) return;
    const float4* b0 = (const float4*)(B + (size_t)(n0 + 0) * ldb);
    const float4* b1 = (const float4*)(B + (size_t)(n0 + 1) * ldb);
    const float4* b2 = (const float4*)(B + (size_t)(n0 + 2) * ldb);
    const float4* b3 = (const float4*)(B + (size_t)(n0 + 3) * ldb);
    const int K4 = K >> 2;
    float acc[8][4] = {};
    for (int i = lane; i < K4; i += 32) {
        float4 v0 = b0[i], v1 = b1[i], v2 = b2[i], v3 = b3[i];
#pragma unroll
        for (int mi = 0; mi < 8; mi++) {
            float4 av = *(const float4*)(A + (size_t)(m0 + mi) * lda + i * 4);
            acc[mi][0] = fmaf(av.x, v0.x, fmaf(av.y, v0.y, fmaf(av.z, v0.z, fmaf(av.w, v0.w, acc[mi][0]))));
            acc[mi][1] = fmaf(av.x, v1.x, fmaf(av.y, v1.y, fmaf(av.z, v1.z, fmaf(av.w, v1.w, acc[mi][1]))));
            acc[mi][2] = fmaf(av.x, v2.x, fmaf(av.y, v2.y, fmaf(av.z, v2.z, fmaf(av.w, v2.w, acc[mi][2]))));
            acc[mi][3] = fmaf(av.x, v3.x, fmaf(av.y, v3.y, fmaf(av.z, v3.z, fmaf(av.w, v3.w, acc[mi][3]))));
        }
    }
#pragma unroll
    for (int mi = 0; mi < 8; mi++)
#pragma unroll
        for (int j = 0; j < 4; j++) {
            float a = acc[mi][j];
#pragma unroll
            for (int o = 16; o; o >>= 1) a += __shfl_xor_sync(0xffffffffu, a, o);
            acc[mi][j] = a;
        }
    if (lane == 0) {
#pragma unroll
        for (int mi = 0; mi < 8; mi++) {
            float* c = C + (size_t)(m0 + mi) * ldc + n0;
            if (bias) {
                c[0] = acc[mi][0] + bias[n0 + 0];
                c[1] = acc[mi][1] + bias[n0 + 1];
                c[2] = acc[mi][2] + bias[n0 + 2];
                c[3] = acc[mi][3] + bias[n0 + 3];
            } else {
                c[0] = acc[mi][0]; c[1] = acc[mi][1];
                c[2] = acc[mi][2]; c[3] = acc[mi][3];
            }
        }
    }
}

// ---------------- attention: flash-style split-S, all fp32 -----------------
// Part kernel: block (blk, b) owns s-rows [blk*25, blk*25+25).
// Phase A: scores (warp per s). Local softmax (m_i, S_i) over 25 rows.
// Phase B: partial weighted sum, re-reading the same rows (L1-resident).
__global__ __launch_bounds__(256)
void attn_part(const float* __restrict__ enc, const float* __restrict__ v,
               const unsigned char* __restrict__ pad,
               float* __restrict__ sc, float* __restrict__ wpart,
               float2* __restrict__ ams)
{
    const int b = blockIdx.y, blk = blockIdx.x;
    const int tid = threadIdx.x;
    const int lane = tid & 31, warp = tid >> 5;
    const int s0 = blk * SROWS;
    __shared__ __align__(16) float vsh[ENCD];
    __shared__ float es[SROWS];

    ((float4*)vsh)[tid] = ((const float4*)(v + (size_t)b * ENCD))[tid];
    __syncthreads();

    const float* encb = enc + ((size_t)b * SS + s0) * ENCD;
    const float4* vv = (const float4*)vsh;
    for (int s = warp; s < SROWS; s += 8) {
        const float4* row = (const float4*)(encb + (size_t)s * ENCD);
        float acc = 0.f;
#pragma unroll
        for (int i = 0; i < ENCD / 128; i++) {
            float4 e4 = row[lane + 32 * i];
            float4 v4 = vv[lane + 32 * i];
            acc = fmaf(e4.x, v4.x, acc);
            acc = fmaf(e4.y, v4.y, acc);
            acc = fmaf(e4.z, v4.z, acc);
            acc = fmaf(e4.w, v4.w, acc);
        }
#pragma unroll
        for (int o = 16; o; o >>= 1) acc += __shfl_xor_sync(0xffffffffu, acc, o);
        if (lane == 0) {
            float sval = pad[(size_t)b * SS + s0 + s] ? -INFINITY : acc;
            es[s] = sval;
            sc[(size_t)b * SS + s0 + s] = sval;   // raw score for combine
        }
    }
    __syncthreads();

    // local softmax over 25 rows (one warp; 25 <= 32)
    if (tid < 32) {
        float sval = (lane < SROWS) ? es[lane] : -INFINITY;
        float mm = sval;
#pragma unroll
        for (int o = 16; o; o >>= 1) mm = fmaxf(mm, __shfl_xor_sync(0xffffffffu, mm, o));
        float ex = (lane < SROWS) ? __expf(sval - mm) : 0.f;
        if (lane < SROWS) es[lane] = ex;
        float ss = ex;
#pragma unroll
        for (int o = 16; o; o >>= 1) ss += __shfl_xor_sync(0xffffffffu, ss, o);
        if (lane == 0) ams[b * NSPLIT + blk] = make_float2(mm, ss);
    }
    __syncthreads();

    // partial weighted: thread owns 4 cols; rows are L1-resident from phase A
    const int e0 = tid * 4;
    const float* p = encb + e0;
    float wx = 0.f, wy = 0.f, wz = 0.f, ww = 0.f;
#pragma unroll
    for (int s = 0; s < SROWS; s++) {
        float e = es[s];
        float4 x = *(const float4*)(p + (size_t)s * ENCD);
        wx = fmaf(e, x.x, wx);
        wy = fmaf(e, x.y, wy);
        wz = fmaf(e, x.z, wz);
        ww = fmaf(e, x.w, ww);
    }
    *(float4*)(wpart + ((size_t)(b * NSPLIT + blk)) * ENCD + e0) =
        make_float4(wx, wy, wz, ww);
}

// Combine kernel: merge 16 partials exactly; write weighted (+a if needed).
__global__ __launch_bounds__(256)
void attn_comb(const float* __restrict__ wpart, const float2* __restrict__ ams,
               float* __restrict__ sc, float* __restrict__ wout, int wstride,
               float* __restrict__ a_out)
{
    const int b = blockIdx.x, tid = threadIdx.x;
    const int lane = tid & 31;
    __shared__ float scl[NSPLIT];
    __shared__ float gmv[2];

    if (tid < 32) {
        float2 p = (lane < NSPLIT) ? ams[b * NSPLIT + lane]
                                   : make_float2(-INFINITY, 0.f);
        float mm = p.x;
#pragma unroll
        for (int o = 16; o; o >>= 1) mm = fmaxf(mm, __shfl_xor_sync(0xffffffffu, mm, o));
        float e = (lane < NSPLIT) ? __expf(p.x - mm) : 0.f;
        float ss = p.y * e;
#pragma unroll
        for (int o = 16; o; o >>= 1) ss += __shfl_xor_sync(0xffffffffu, ss, o);
        if (lane < NSPLIT) scl[lane] = e;
        if (lane == 0) { gmv[0] = mm; gmv[1] = ss; }
    }
    __syncthreads();
    const float gm = gmv[0];
    const float inv = 1.f / gmv[1];

    // weighted: thread owns 4 cols, sum 16 partials
    const int e0 = tid * 4;
    float wx = 0.f, wy = 0.f, wz = 0.f, ww = 0.f;
#pragma unroll
    for (int i = 0; i < NSPLIT; i++) {
        float e = scl[i];
        float4 x = *(const float4*)(wpart + ((size_t)(b * NSPLIT + i)) * ENCD + e0);
        wx = fmaf(e, x.x, wx);
        wy = fmaf(e, x.y, wy);
        wz = fmaf(e, x.z, wz);
        ww = fmaf(e, x.w, ww);
    }
    *(float4*)(wout + (size_t)b * wstride + e0) =
        make_float4(wx * inv, wy * inv, wz * inv, ww * inv);

    if (a_out) {
        for (int s = tid; s < SS; s += 256)
            a_out[(size_t)b * SS + s] = __expf(sc[(size_t)b * SS + s] - gm) * inv;
    }
}

// ---------------- small elementwise / glue kernels -------------------------
__global__ void embed_copy(const float* __restrict__ emb)
{
    int i = blockIdx.x * blockDim.x + threadIdx.x;
    if (i < BB * EMBD) {
        int b = i / EMBD, j = i - b * EMBD;
        g_rnn[(size_t)b * RNNK + j] = emb[i];
    }
}

__global__ void gru_combine(const float* __restrict__ h1,
                            float* __restrict__ out_h, int write_out)
{
    int i = blockIdx.x * blockDim.x + threadIdx.x;
    if (i >= BB * DECD) return;
    int b = i / DECD, j = i - b * DECD;
    const float* gx = g_gx + (size_t)b * G3;
    const float* gh = g_gh + (size_t)b * G3;
    float r = 1.f / (1.f + __expf(-(gx[j] + gh[j])));
    float z = 1.f / (1.f + __expf(-(gx[j + DECD] + gh[j + DECD])));
    float n = tanhf(gx[j + 2 * DECD] + r * gh[j + 2 * DECD]);
    float h = (1.f - z) * n + z * h1[i];
    g_hw[(size_t)b * HWK + j] = h;
    if (write_out) out_h[i] = h;
}

__global__ __launch_bounds__(128)
void pgen_kernel(const float* __restrict__ Wp, const float* __restrict__ bp)
{
    int b = blockIdx.x, tid = threadIdx.x;
    int lane = tid & 31, warp = tid >> 5;
    __shared__ float red[4];
    const float* hwb = g_hw + (size_t)b * HWK;
    float acc = 0.f;
    for (int i = tid; i < HWK; i += 128) acc = fmaf(hwb[i], Wp[i], acc);
#pragma unroll
    for (int o = 16; o; o >>= 1) acc += __shfl_xor_sync(0xffffffffu, acc, o);
    if (lane == 0) red[warp] = acc;
    __syncthreads();
    if (tid == 0) {
        float t = red[0] + red[1] + red[2] + red[3] + bp[0];
        g_pgen[b] = 1.f / (1.f + __expf(-t));
    }
}

// ---------------- pvocab: partial / combine / write (full parallelism) -----
__global__ __launch_bounds__(256)
void pv_part()
{
    const int b = blockIdx.y, c = blockIdx.x;
    const int tid = threadIdx.x;
    const int lane = tid & 31, warp = tid >> 5;
    __shared__ float rm[8], rs[8];
    const float* lg = g_logits + (size_t)b * VOCAB + c * 1000;
    float m = -INFINITY, s = 0.f;
    for (int i = tid; i < 1000; i += 256) {
        float x = lg[i];
        float mo = m;
        m = fmaxf(m, x);
        s = s * __expf(mo - m) + __expf(x - m);
    }
#pragma unroll
    for (int o = 16; o; o >>= 1) {
        float m2 = __shfl_xor_sync(0xffffffffu, m, o);
        float s2 = __shfl_xor_sync(0xffffffffu, s, o);
        float M = fmaxf(m, m2);
        s = s * __expf(m - M) + s2 * __expf(m2 - M);
        m = M;
    }
    if (lane == 0) { rm[warp] = m; rs[warp] = s; }
    __syncthreads();
    if (tid == 0) {
        float M = rm[0], S = rs[0];
        for (int w = 1; w < 8; w++) {
            float M2 = fmaxf(M, rm[w]);
            S = S * __expf(M - M2) + rs[w] * __expf(rm[w] - M2);
            M = M2;
        }
        g_pm[b * PVCH + c] = M;
        g_ps[b * PVCH + c] = S;
    }
}

__global__ __launch_bounds__(32)
void pv_comb()
{
    const int b = blockIdx.x, lane = threadIdx.x;
    float m = -INFINITY, s = 0.f;
    for (int i = lane; i < PVCH; i += 32) {
        float m2 = g_pm[b * PVCH + i], s2 = g_ps[b * PVCH + i];
        float M = fmaxf(m, m2);
        s = s * __expf(m - M) + s2 * __expf(m2 - M);
        m = M;
    }
#pragma unroll
    for (int o = 16; o; o >>= 1) {
        float m2 = __shfl_xor_sync(0xffffffffu, m, o);
        float s2 = __shfl_xor_sync(0xffffffffu, s, o);
        float M = fmaxf(m, m2);
        s = s * __expf(m - M) + s2 * __expf(m2 - M);
        m = M;
    }
    if (lane == 0) g_pms[b] = make_float2(m, g_pgen[b] / s);
}

__global__ __launch_bounds__(256)
void pv_write(float* __restrict__ pout)
{
    const int b = blockIdx.y, c = blockIdx.x;
    const int tid = threadIdx.x;
    float2 t = g_pms[b];
    const float m = t.x, scale = t.y;
    const float* lg = g_logits + (size_t)b * VOCAB + c * 1000;
    float* row = pout + (size_t)b * PVC;
    float* ro = row + c * 1000;
    for (int i = tid; i < 1000; i += 256) ro[i] = __expf(lg[i] - m) * scale;
    if (c == PVCH - 1)
        for (int i = VOCAB + tid; i < PVC; i += 256) row[i] = 0.f;
}

__global__ void scatter_kernel(const int* __restrict__ src, float* __restrict__ pout)
{
    int i = blockIdx.x * blockDim.x + threadIdx.x;
    if (i >= BB * SS) return;
    int b = i / SS;
    float val = (1.f - g_pgen[b]) * g_a2[i];
    atomicAdd(pout + (size_t)b * PVC + src[i], val);
}

// ---------------- launch ---------------------------------------------------
extern "C" void kernel_launch(void* const* d_in, const int* in_sizes, int n_in,
                              void* d_out, int out_size)
{
    int off = (n_in >= 16) ? 0 : -1;
    const float* embedded = (const float*)d_in[0];
    const float* enc      = (const float*)d_in[1];
    const float* h1       = (const float*)d_in[2];
    const unsigned char* pad = (const unsigned char*)d_in[3];
    const int*   src      = (const int*)d_in[5 + off];
    const float* W_attn1  = (const float*)d_in[6 + off];
    const float* W_attn2  = (const float*)d_in[7 + off];
    const float* W_ih     = (const float*)d_in[8 + off];
    const float* W_hh     = (const float*)d_in[9 + off];
    const float* b_ih     = (const float*)d_in[10 + off];
    const float* b_hh     = (const float*)d_in[11 + off];
    const float* W_out    = (const float*)d_in[12 + off];
    const float* b_out    = (const float*)d_in[13 + off];
    const float* W_p      = (const float*)d_in[14 + off];
    const float* b_p      = (const float*)d_in[15 + off];
    float* pout = (float*)d_out;

    float *v, *rnn, *gx, *gh, *hw, *logits, *sc, *a2, *wpart;
    float2* ams;
    cudaGetSymbolAddress((void**)&v, g_v);
    cudaGetSymbolAddress((void**)&rnn, g_rnn);
    cudaGetSymbolAddress((void**)&gx, g_gx);
    cudaGetSymbolAddress((void**)&gh, g_gh);
    cudaGetSymbolAddress((void**)&hw, g_hw);
    cudaGetSymbolAddress((void**)&logits, g_logits);
    cudaGetSymbolAddress((void**)&sc, g_sc);
    cudaGetSymbolAddress((void**)&a2, g_a2);
    cudaGetSymbolAddress((void**)&wpart, g_wpart);
    cudaGetSymbolAddress((void**)&ams, g_ams);

    cudaFuncSetAttribute(gemm_mma, cudaFuncAttributeMaxDynamicSharedMemorySize, MM_SMEM);

    // 1. rnn[:, 0:EMB] = embedded
    embed_copy<<<(BB * EMBD + 255) / 256, 256>>>(embedded);
    // 2. gh = h1 @ W_hh^T + b_hh
    gemm_warp8m<<<dim3((G3 + 31) / 32, BB / 8), 256>>>(h1, DECD, W_hh, DECD,
                                                       gh, G3, b_hh, G3, DECD);
    // 3. v1 = h1 @ W_attn1^T
    gemm_warp8m<<<dim3(ENCD / 32, BB / 8), 256>>>(h1, DECD, W_attn1, DECD,
                                                  v, ENCD, nullptr, ENCD, DECD);
    // 4. attention 1 (flash split-S): one enc read -> weighted1 into rnn
    attn_part<<<dim3(NSPLIT, BB), 256>>>(enc, v, pad, sc, wpart, ams);
    attn_comb<<<BB, 256>>>(wpart, ams, sc, rnn + EMBD, RNNK, nullptr);
    // 5. gx = rnn @ W_ih^T + b_ih
    gemm_warp8m<<<dim3((G3 + 31) / 32, BB / 8), 256>>>(rnn, RNNK, W_ih, RNNK,
                                                       gx, G3, b_ih, G3, RNNK);
    // 6. GRU combine -> hw[:, 0:DEC] (= h_new)
    int wtail = (out_size >= BB * PVC + BB * DECD) ? 1 : 0;
    gru_combine<<<(BB * DECD + 255) / 256, 256>>>(h1, pout + (size_t)BB * PVC, wtail);
    // 7. v2 = h_new @ W_attn2^T
    gemm_warp8m<<<dim3(ENCD / 32, BB / 8), 256>>>(hw, HWK, W_attn2, DECD,
                                                  v, ENCD, nullptr, ENCD, DECD);
    // 8. attention 2 (flash split-S): weighted2 into hw, a2 saved
    attn_part<<<dim3(NSPLIT, BB), 256>>>(enc, v, pad, sc, wpart, ams);
    attn_comb<<<BB, 256>>>(wpart, ams, sc, hw + DECD, HWK, a2);
    // 9. p_gen
    pgen_kernel<<<BB, 128>>>(W_p, b_p);
    // 10. convert A once (fp16), then logits = hw @ W_out^T + b_out
    convA_kernel<<<BB, 256>>>();
    gemm_mma<<<dim3((VOCAB + 127) / 128), 256, MM_SMEM>>>(W_out, HWK, logits,
                                                          VOCAB, b_out, VOCAB, HWK);
    // 11. p_out = p_gen * softmax(logits) — partial/combine/write
    pv_part<<<dim3(PVCH, BB), 256>>>();
    pv_comb<<<BB, 32>>>();
    pv_write<<<dim3(PVCH, BB), 256>>>(pout);
    // 12. scatter-add (1-p_gen)*a2 at source ids
    scatter_kernel<<<(BB * SS + 255) / 256, 256>>>(src, pout);
}